// round 1
// baseline (speedup 1.0000x reference)
#include <cuda_runtime.h>
#include <math.h>

#define BATCH   4096
#define SEQ     64
#define CDIM    256
#define HEADS   8
#define HDIM    32
#define NW      64
#define MROWS   (BATCH * SEQ)        // 262144
#define QKVDIM  768

// Scratch (device globals; no runtime allocation allowed)
__device__ float g_qkv[(size_t)MROWS * QKVDIM];  // [M, 768]  q|k|v, head-major
__device__ float g_att[(size_t)MROWS * CDIM];    // [M, 256]  attention output (b,n,h*32+d)

// ---------------------------------------------------------------------------
// SGEMM: C[M,Ncols] = A[M,K] @ W[Ncols,K]^T + bias[Ncols]
// BM=128, BN=64, BK=16, 256 threads, 8x4 per-thread microtile
// ---------------------------------------------------------------------------
#define BM 128
#define BN 64
#define BK 16
#define TM 8
#define TN 4

__global__ __launch_bounds__(256)
void sgemm_bias_kernel(const float* __restrict__ A,
                       const float* __restrict__ W,
                       const float* __restrict__ bias,
                       float* __restrict__ C,
                       int M, int Ncols, int K)
{
    __shared__ float As[BK][BM + 4];
    __shared__ float Bs[BK][BN + 4];

    const int tid = threadIdx.x;
    const int tx  = tid & 15;        // 0..15  (N direction)
    const int ty  = tid >> 4;        // 0..15  (M direction)
    const int row0 = blockIdx.y * BM;
    const int col0 = blockIdx.x * BN;

    float acc[TM][TN];
#pragma unroll
    for (int r = 0; r < TM; r++)
#pragma unroll
        for (int c = 0; c < TN; c++) acc[r][c] = 0.f;

    for (int k0 = 0; k0 < K; k0 += BK) {
        // Load A tile: 128x16 = 512 float4, 2 per thread
#pragma unroll
        for (int i = 0; i < 2; i++) {
            int idx = tid * 2 + i;           // 0..511
            int r   = idx >> 2;              // 0..127
            int kc  = (idx & 3) * 4;         // 0,4,8,12
            float4 v = *(const float4*)&A[(size_t)(row0 + r) * K + k0 + kc];
            As[kc + 0][r] = v.x; As[kc + 1][r] = v.y;
            As[kc + 2][r] = v.z; As[kc + 3][r] = v.w;
        }
        // Load W tile: 64x16 = 256 float4, 1 per thread
        {
            int n  = tid >> 2;               // 0..63
            int kc = (tid & 3) * 4;
            float4 v = *(const float4*)&W[(size_t)(col0 + n) * K + k0 + kc];
            Bs[kc + 0][n] = v.x; Bs[kc + 1][n] = v.y;
            Bs[kc + 2][n] = v.z; Bs[kc + 3][n] = v.w;
        }
        __syncthreads();

#pragma unroll
        for (int kk = 0; kk < BK; kk++) {
            float a[TM], b[TN];
#pragma unroll
            for (int r = 0; r < TM; r++) a[r] = As[kk][ty * TM + r];
#pragma unroll
            for (int c = 0; c < TN; c++) b[c] = Bs[kk][tx * TN + c];
#pragma unroll
            for (int r = 0; r < TM; r++)
#pragma unroll
                for (int c = 0; c < TN; c++) acc[r][c] += a[r] * b[c];
        }
        __syncthreads();
    }

    // Epilogue with bias
#pragma unroll
    for (int r = 0; r < TM; r++) {
        int row = row0 + ty * TM + r;
#pragma unroll
        for (int c = 0; c < TN; c++) {
            int col = col0 + tx * TN + c;
            C[(size_t)row * Ncols + col] = acc[r][c] + bias[col];
        }
    }
}

// ---------------------------------------------------------------------------
// Fused attention: RoPE + cosine-norm + scores + mask + softmax + AV
// One CTA per (window b, head h). 256 threads.
// ---------------------------------------------------------------------------
__global__ __launch_bounds__(256)
void attn_kernel(const float* __restrict__ mask,
                 const float* __restrict__ logit_scale)
{
    const int b = blockIdx.x;        // 0..4095
    const int h = blockIdx.y;        // 0..7
    const int tid = threadIdx.x;

    __shared__ float qs[SEQ][HDIM + 1];
    __shared__ float ks[SEQ][HDIM + 1];
    __shared__ float vs[SEQ][HDIM + 1];
    __shared__ float ps[SEQ][SEQ + 1];

    // ---- load q,k,v tiles for this (b,h) ----
    for (int i = tid; i < SEQ * HDIM; i += 256) {
        int n = i >> 5;
        int d = i & 31;
        size_t base = ((size_t)(b * SEQ + n)) * QKVDIM + h * HDIM + d;
        qs[n][d] = g_qkv[base];
        ks[n][d] = g_qkv[base + 256];
        vs[n][d] = g_qkv[base + 512];
    }
    __syncthreads();

    // ---- RoPE + L2-normalize q and k (128 row-tasks) ----
    if (tid < 128) {
        int n = tid & 63;
        float (*buf)[HDIM + 1] = (tid < 64) ? qs : ks;
        float tmp[HDIM];
        const float t = (float)n + 0.1f;                 // VIEW_ID * VIEW_OFFSET
        const float NEG_LN1E4_OVER16 = -0.57564627324851142f; // -ln(10000)/16
#pragma unroll
        for (int f = 0; f < 16; f++) {
            float inv = expf((float)f * NEG_LN1E4_OVER16);
            float s, c;
            sincosf(t * inv, &s, &c);
            float x1 = buf[n][f];
            float x2 = buf[n][f + 16];
            tmp[f]      = x1 * c - x2 * s;
            tmp[f + 16] = x1 * s + x2 * c;
        }
        float ss = 0.f;
#pragma unroll
        for (int d = 0; d < HDIM; d++) ss += tmp[d] * tmp[d];
        float nrm = fmaxf(sqrtf(ss), 1e-12f);
        float inv = 1.f / nrm;
#pragma unroll
        for (int d = 0; d < HDIM; d++) buf[n][d] = tmp[d] * inv;
    }
    __syncthreads();

    // ---- scores + mask ----
    const float MAX_LOGIT = 4.6051701859880914f;        // ln(100)
    const float scale = expf(fminf(logit_scale[h], MAX_LOGIT));
    const int w = b & (NW - 1);
    const float* mrow = mask + (size_t)w * SEQ * SEQ;

    const int i  = tid >> 2;          // row 0..63
    const int jb = (tid & 3) * 16;    // 16-col strip

#pragma unroll 4
    for (int jj = 0; jj < 16; jj++) {
        int j = jb + jj;
        float acc = 0.f;
#pragma unroll
        for (int d = 0; d < HDIM; d++) acc += qs[i][d] * ks[j][d];
        ps[i][j] = acc * scale + mrow[i * SEQ + j];
    }
    __syncwarp();

    // ---- softmax over row i (4 lanes per row, lane-aligned groups) ----
    float mx = -1e30f;
#pragma unroll
    for (int jj = 0; jj < 16; jj++) mx = fmaxf(mx, ps[i][jb + jj]);
    mx = fmaxf(mx, __shfl_xor_sync(0xffffffffu, mx, 1));
    mx = fmaxf(mx, __shfl_xor_sync(0xffffffffu, mx, 2));

    float sum = 0.f;
#pragma unroll
    for (int jj = 0; jj < 16; jj++) {
        float e = expf(ps[i][jb + jj] - mx);
        ps[i][jb + jj] = e;
        sum += e;
    }
    sum += __shfl_xor_sync(0xffffffffu, sum, 1);
    sum += __shfl_xor_sync(0xffffffffu, sum, 2);
    float isum = 1.f / sum;
#pragma unroll
    for (int jj = 0; jj < 16; jj++) ps[i][jb + jj] *= isum;
    __syncwarp();

    // ---- AV: thread computes out[i][dbase..dbase+8) ----
    const int dbase = (tid & 3) * 8;
    float outv[8];
#pragma unroll
    for (int dd = 0; dd < 8; dd++) outv[dd] = 0.f;
    for (int j = 0; j < SEQ; j++) {
        float p = ps[i][j];
#pragma unroll
        for (int dd = 0; dd < 8; dd++) outv[dd] += p * vs[j][dbase + dd];
    }
    size_t obase = ((size_t)(b * SEQ + i)) * CDIM + h * HDIM + dbase;
#pragma unroll
    for (int dd = 0; dd < 8; dd++) g_att[obase + dd] = outv[dd];
}

// ---------------------------------------------------------------------------
extern "C" void kernel_launch(void* const* d_in, const int* in_sizes, int n_in,
                              void* d_out, int out_size)
{
    const float* x           = (const float*)d_in[0];
    const float* mask        = (const float*)d_in[1];
    const float* qkv_w       = (const float*)d_in[2];
    const float* qkv_b       = (const float*)d_in[3];
    const float* proj_w      = (const float*)d_in[4];
    const float* proj_b      = (const float*)d_in[5];
    const float* logit_scale = (const float*)d_in[6];
    float* out = (float*)d_out;

    float* qkv_ptr = nullptr;
    float* att_ptr = nullptr;
    cudaGetSymbolAddress((void**)&qkv_ptr, g_qkv);
    cudaGetSymbolAddress((void**)&att_ptr, g_att);

    // 1) QKV GEMM: [262144,256] x [256,768]^T + bias
    {
        dim3 grid(QKVDIM / BN, MROWS / BM);
        sgemm_bias_kernel<<<grid, 256>>>(x, qkv_w, qkv_b, qkv_ptr,
                                         MROWS, QKVDIM, CDIM);
    }
    // 2) Fused attention per (b,h)
    {
        dim3 grid(BATCH, HEADS);
        attn_kernel<<<grid, 256>>>(mask, logit_scale);
    }
    // 3) Proj GEMM: [262144,256] x [256,256]^T + bias
    {
        dim3 grid(CDIM / BN, MROWS / BM);
        sgemm_bias_kernel<<<grid, 256>>>(att_ptr, proj_w, proj_b, out,
                                         MROWS, CDIM, CDIM);
    }
}

// round 3
// speedup vs baseline: 1.5030x; 1.5030x over previous
#include <cuda_runtime.h>
#include <cuda_bf16.h>
#include <math.h>
#include <stdint.h>

#define BATCH   4096
#define SEQ     64
#define CDIM    256
#define HEADS   8
#define HDIM    32
#define NW      64
#define MROWS   (BATCH * SEQ)        // 262144
#define QKVDIM  768
#define GK      256                  // K of both GEMMs

// Scratch (device globals; no runtime allocation allowed)
__device__ float g_qkv[(size_t)MROWS * QKVDIM];  // [M, 768]  q|k|v, head-major
__device__ float g_att[(size_t)MROWS * CDIM];    // [M, 256]  attention output
__device__ float g_rope_cos[SEQ * 16];
__device__ float g_rope_sin[SEQ * 16];

#define SW128(b) ((b) ^ (((b) >> 3) & 0x70))

__device__ __forceinline__ uint32_t smem_u32(const void* p) {
    uint32_t a;
    asm("{ .reg .u64 t; cvta.to.shared.u64 t, %1; cvt.u32.u64 %0, t; }"
        : "=r"(a) : "l"(p));
    return a;
}

__device__ __forceinline__ void ldmatrix_x4(uint32_t* r, uint32_t addr) {
    asm volatile("ldmatrix.sync.aligned.m8n8.x4.shared.b16 {%0,%1,%2,%3}, [%4];"
                 : "=r"(r[0]), "=r"(r[1]), "=r"(r[2]), "=r"(r[3]) : "r"(addr));
}

__device__ __forceinline__ void mma_bf16(float* c, const uint32_t* a,
                                         const uint32_t* b) {
    asm volatile(
        "mma.sync.aligned.m16n8k16.row.col.f32.bf16.bf16.f32 "
        "{%0,%1,%2,%3}, {%4,%5,%6,%7}, {%8,%9}, {%0,%1,%2,%3};"
        : "+f"(c[0]), "+f"(c[1]), "+f"(c[2]), "+f"(c[3])
        : "r"(a[0]), "r"(a[1]), "r"(a[2]), "r"(a[3]), "r"(b[0]), "r"(b[1]));
}

// ===========================================================================
// mma.sync bf16-split GEMM: C[M,N] = A[M,K] @ W[N,K]^T + bias
// K=256, BM=128, BN=64, KC=64. 256 threads, warp grid 4(M) x 2(N),
// warp tile 32x32 (2 m16-tiles x 4 n8-tiles). 3 MMAs per tile (hi/mid split).
// ===========================================================================
#define KC       64
#define SA_HI    0
#define SA_MID   16384
#define SB_HI    32768
#define SB_MID   40960
#define SMEM_GEMM_BYTES 49152

__global__ void __launch_bounds__(256, 2)
mma_gemm_kernel(const float* __restrict__ A,
                const float* __restrict__ W,
                const float* __restrict__ bias,
                float* __restrict__ C,
                int Ncols)
{
    extern __shared__ char smem[];
    const uint32_t sb = smem_u32(smem);
    const int tid  = threadIdx.x;
    const int wid  = tid >> 5;
    const int lane = tid & 31;
    const int wm   = wid & 3;          // 0..3  (M)
    const int wn   = wid >> 2;         // 0..1  (N)
    const int row0 = blockIdx.y * 128;
    const int col0 = blockIdx.x * 64;

    float acc[2][4][4];
#pragma unroll
    for (int mt = 0; mt < 2; mt++)
#pragma unroll
        for (int nt = 0; nt < 4; nt++)
#pragma unroll
            for (int e = 0; e < 4; e++) acc[mt][nt][e] = 0.f;

    const float* Abase = A + (size_t)row0 * GK;
    const float* Wbase = W + (size_t)col0 * GK;

    // fragment smem addresses (fixed per thread, chunk-invariant except ks)
    const int arow = wm * 32 + (lane & 15);
    const int acol8 = (lane >> 4) * 8;                    // 0 or 8
    const int bn_lo = wn * 32 + ((lane >> 4) << 3) + (lane & 7);
    const int bc8   = ((lane >> 3) & 1) << 3;             // 0 or 8

    for (int chunk = 0; chunk < GK / KC; chunk++) {
        const int k0 = chunk * KC;
        // ---- convert A tile 128x64 f32 -> hi/mid bf16 (8 float4/thread)
#pragma unroll
        for (int i = 0; i < 8; i++) {
            int idx = i * 256 + tid;
            int r   = idx >> 4;
            int c4  = idx & 15;
            float4 v = *(const float4*)&Abase[(size_t)r * GK + k0 + c4 * 4];
            __nv_bfloat16 h0 = __float2bfloat16(v.x);
            __nv_bfloat16 h1 = __float2bfloat16(v.y);
            __nv_bfloat16 h2 = __float2bfloat16(v.z);
            __nv_bfloat16 h3 = __float2bfloat16(v.w);
            __nv_bfloat16 m0 = __float2bfloat16(v.x - __bfloat162float(h0));
            __nv_bfloat16 m1 = __float2bfloat16(v.y - __bfloat162float(h1));
            __nv_bfloat16 m2 = __float2bfloat16(v.z - __bfloat162float(h2));
            __nv_bfloat16 m3 = __float2bfloat16(v.w - __bfloat162float(h3));
            uint32_t boff = SW128((uint32_t)(r * 128 + c4 * 8));
            uint2 hv, mv;
            hv.x = (uint32_t)__bfloat16_as_ushort(h0) |
                   ((uint32_t)__bfloat16_as_ushort(h1) << 16);
            hv.y = (uint32_t)__bfloat16_as_ushort(h2) |
                   ((uint32_t)__bfloat16_as_ushort(h3) << 16);
            mv.x = (uint32_t)__bfloat16_as_ushort(m0) |
                   ((uint32_t)__bfloat16_as_ushort(m1) << 16);
            mv.y = (uint32_t)__bfloat16_as_ushort(m2) |
                   ((uint32_t)__bfloat16_as_ushort(m3) << 16);
            *(uint2*)(smem + SA_HI  + boff) = hv;
            *(uint2*)(smem + SA_MID + boff) = mv;
        }
        // ---- convert B tile 64x64 (4 float4/thread)
#pragma unroll
        for (int i = 0; i < 4; i++) {
            int idx = i * 256 + tid;
            int r   = idx >> 4;
            int c4  = idx & 15;
            float4 v = *(const float4*)&Wbase[(size_t)r * GK + k0 + c4 * 4];
            __nv_bfloat16 h0 = __float2bfloat16(v.x);
            __nv_bfloat16 h1 = __float2bfloat16(v.y);
            __nv_bfloat16 h2 = __float2bfloat16(v.z);
            __nv_bfloat16 h3 = __float2bfloat16(v.w);
            __nv_bfloat16 m0 = __float2bfloat16(v.x - __bfloat162float(h0));
            __nv_bfloat16 m1 = __float2bfloat16(v.y - __bfloat162float(h1));
            __nv_bfloat16 m2 = __float2bfloat16(v.z - __bfloat162float(h2));
            __nv_bfloat16 m3 = __float2bfloat16(v.w - __bfloat162float(h3));
            uint32_t boff = SW128((uint32_t)(r * 128 + c4 * 8));
            uint2 hv, mv;
            hv.x = (uint32_t)__bfloat16_as_ushort(h0) |
                   ((uint32_t)__bfloat16_as_ushort(h1) << 16);
            hv.y = (uint32_t)__bfloat16_as_ushort(h2) |
                   ((uint32_t)__bfloat16_as_ushort(h3) << 16);
            mv.x = (uint32_t)__bfloat16_as_ushort(m0) |
                   ((uint32_t)__bfloat16_as_ushort(m1) << 16);
            mv.y = (uint32_t)__bfloat16_as_ushort(m2) |
                   ((uint32_t)__bfloat16_as_ushort(m3) << 16);
            *(uint2*)(smem + SB_HI  + boff) = hv;
            *(uint2*)(smem + SB_MID + boff) = mv;
        }
        __syncthreads();

        // ---- 4 k-steps of m16n8k16
#pragma unroll
        for (int ks = 0; ks < 4; ks++) {
            uint32_t ah[2][4], am[2][4], bh[2][4], bm[2][4];
            const int kcA = ks * 16 + acol8;
#pragma unroll
            for (int mt = 0; mt < 2; mt++) {
                uint32_t off = SW128((uint32_t)((arow + mt * 16) * 128 + kcA * 2));
                ldmatrix_x4(ah[mt], sb + SA_HI  + off);
                ldmatrix_x4(am[mt], sb + SA_MID + off);
            }
            const int kcB = ks * 16 + bc8;
#pragma unroll
            for (int pp = 0; pp < 2; pp++) {
                uint32_t off = SW128((uint32_t)((bn_lo + pp * 16) * 128 + kcB * 2));
                ldmatrix_x4(bh[pp], sb + SB_HI  + off);
                ldmatrix_x4(bm[pp], sb + SB_MID + off);
            }
#pragma unroll
            for (int mt = 0; mt < 2; mt++)
#pragma unroll
                for (int nt = 0; nt < 4; nt++) {
                    const uint32_t* bhp = &bh[nt >> 1][(nt & 1) * 2];
                    const uint32_t* bmp = &bm[nt >> 1][(nt & 1) * 2];
                    mma_bf16(acc[mt][nt], ah[mt], bhp);
                    mma_bf16(acc[mt][nt], ah[mt], bmp);
                    mma_bf16(acc[mt][nt], am[mt], bhp);
                }
        }
        __syncthreads();
    }

    // ---- epilogue: write 32x32 warp tile with bias
#pragma unroll
    for (int mt = 0; mt < 2; mt++) {
        int r_ = row0 + wm * 32 + mt * 16 + (lane >> 2);
#pragma unroll
        for (int nt = 0; nt < 4; nt++) {
            int c_ = col0 + wn * 32 + nt * 8 + (lane & 3) * 2;
            float2 bv = *(const float2*)&bias[c_];
            float2 o0, o1;
            o0.x = acc[mt][nt][0] + bv.x;
            o0.y = acc[mt][nt][1] + bv.y;
            o1.x = acc[mt][nt][2] + bv.x;
            o1.y = acc[mt][nt][3] + bv.y;
            *(float2*)&C[(size_t)r_ * Ncols + c_]       = o0;
            *(float2*)&C[(size_t)(r_ + 8) * Ncols + c_] = o1;
        }
    }
}

// ---------------------------------------------------------------------------
// RoPE table init (cos/sin depend only on (n, f); shared by all CTAs)
// ---------------------------------------------------------------------------
__global__ void rope_init_kernel()
{
    int i = threadIdx.x;            // 0..1023
    int n = i >> 4;
    int f = i & 15;
    const float NEG_LN1E4_OVER16 = -0.57564627324851142f;  // -ln(10000)/16
    float inv = expf((float)f * NEG_LN1E4_OVER16);
    float t = (float)n + 0.1f;                              // VIEW_ID*VIEW_OFFSET
    float s, c;
    sincosf(t * inv, &s, &c);
    g_rope_cos[i] = c;
    g_rope_sin[i] = s;
}

// ---------------------------------------------------------------------------
// Fused attention: RoPE(table) + cosine-norm + scores + mask + softmax + AV
// One CTA per (window b, head h). 256 threads.
// ---------------------------------------------------------------------------
__global__ __launch_bounds__(256)
void attn_kernel(const float* __restrict__ mask,
                 const float* __restrict__ logit_scale)
{
    const int b = blockIdx.x;
    const int h = blockIdx.y;
    const int tid = threadIdx.x;

    __shared__ float qs[SEQ][HDIM + 1];
    __shared__ float ks[SEQ][HDIM + 1];
    __shared__ float vs[SEQ][HDIM + 1];
    __shared__ float ps[SEQ][SEQ + 1];

    for (int i = tid; i < SEQ * HDIM; i += 256) {
        int n = i >> 5;
        int d = i & 31;
        size_t base = ((size_t)(b * SEQ + n)) * QKVDIM + h * HDIM + d;
        qs[n][d] = g_qkv[base];
        ks[n][d] = g_qkv[base + 256];
        vs[n][d] = g_qkv[base + 512];
    }
    __syncthreads();

    // ---- RoPE (table) + L2-normalize q and k (128 row-tasks) ----
    if (tid < 128) {
        int n = tid & 63;
        float (*buf)[HDIM + 1] = (tid < 64) ? qs : ks;
        float tmp[HDIM];
#pragma unroll
        for (int f = 0; f < 16; f++) {
            float c = g_rope_cos[n * 16 + f];
            float s = g_rope_sin[n * 16 + f];
            float x1 = buf[n][f];
            float x2 = buf[n][f + 16];
            tmp[f]      = x1 * c - x2 * s;
            tmp[f + 16] = x1 * s + x2 * c;
        }
        float ss = 0.f;
#pragma unroll
        for (int d = 0; d < HDIM; d++) ss += tmp[d] * tmp[d];
        float inv = rsqrtf(fmaxf(ss, 1e-24f));
#pragma unroll
        for (int d = 0; d < HDIM; d++) buf[n][d] = tmp[d] * inv;
    }
    __syncthreads();

    const float MAX_LOGIT = 4.6051701859880914f;          // ln(100)
    const float scale = __expf(fminf(logit_scale[h], MAX_LOGIT));
    const int w = b & (NW - 1);
    const float* mrow = mask + (size_t)w * SEQ * SEQ;

    const int i  = tid >> 2;
    const int jb = (tid & 3) * 16;

#pragma unroll 4
    for (int jj = 0; jj < 16; jj++) {
        int j = jb + jj;
        float acc = 0.f;
#pragma unroll
        for (int d = 0; d < HDIM; d++) acc += qs[i][d] * ks[j][d];
        ps[i][j] = acc * scale + mrow[i * SEQ + j];
    }
    __syncwarp();

    float mx = -1e30f;
#pragma unroll
    for (int jj = 0; jj < 16; jj++) mx = fmaxf(mx, ps[i][jb + jj]);
    mx = fmaxf(mx, __shfl_xor_sync(0xffffffffu, mx, 1));
    mx = fmaxf(mx, __shfl_xor_sync(0xffffffffu, mx, 2));

    float sum = 0.f;
#pragma unroll
    for (int jj = 0; jj < 16; jj++) {
        float e = __expf(ps[i][jb + jj] - mx);
        ps[i][jb + jj] = e;
        sum += e;
    }
    sum += __shfl_xor_sync(0xffffffffu, sum, 1);
    sum += __shfl_xor_sync(0xffffffffu, sum, 2);
    float isum = 1.f / sum;
#pragma unroll
    for (int jj = 0; jj < 16; jj++) ps[i][jb + jj] *= isum;
    __syncwarp();

    const int dbase = (tid & 3) * 8;
    float outv[8];
#pragma unroll
    for (int dd = 0; dd < 8; dd++) outv[dd] = 0.f;
    for (int j = 0; j < SEQ; j++) {
        float p = ps[i][j];
#pragma unroll
        for (int dd = 0; dd < 8; dd++) outv[dd] += p * vs[j][dbase + dd];
    }
    size_t obase = ((size_t)(b * SEQ + i)) * CDIM + h * HDIM + dbase;
#pragma unroll
    for (int dd = 0; dd < 8; dd++) g_att[obase + dd] = outv[dd];
}

// ---------------------------------------------------------------------------
extern "C" void kernel_launch(void* const* d_in, const int* in_sizes, int n_in,
                              void* d_out, int out_size)
{
    const float* x           = (const float*)d_in[0];
    const float* mask        = (const float*)d_in[1];
    const float* qkv_w       = (const float*)d_in[2];
    const float* qkv_b       = (const float*)d_in[3];
    const float* proj_w      = (const float*)d_in[4];
    const float* proj_b      = (const float*)d_in[5];
    const float* logit_scale = (const float*)d_in[6];
    float* out = (float*)d_out;

    float* qkv_ptr = nullptr;
    float* att_ptr = nullptr;
    cudaGetSymbolAddress((void**)&qkv_ptr, g_qkv);
    cudaGetSymbolAddress((void**)&att_ptr, g_att);

    cudaFuncSetAttribute(mma_gemm_kernel,
                         cudaFuncAttributeMaxDynamicSharedMemorySize,
                         SMEM_GEMM_BYTES);

    // 0) RoPE table
    rope_init_kernel<<<1, 1024>>>();

    // 1) QKV GEMM: [262144,256] x [256,768]^T + bias
    {
        dim3 grid(QKVDIM / 64, MROWS / 128);
        mma_gemm_kernel<<<grid, 256, SMEM_GEMM_BYTES>>>(x, qkv_w, qkv_b,
                                                        qkv_ptr, QKVDIM);
    }
    // 2) Fused attention per (b,h)
    {
        dim3 grid(BATCH, HEADS);
        attn_kernel<<<grid, 256>>>(mask, logit_scale);
    }
    // 3) Proj GEMM: [262144,256] x [256,256]^T + bias
    {
        dim3 grid(CDIM / 64, MROWS / 128);
        mma_gemm_kernel<<<grid, 256, SMEM_GEMM_BYTES>>>(att_ptr, proj_w, proj_b,
                                                        out, CDIM);
    }
}

// round 4
// speedup vs baseline: 2.2463x; 1.4945x over previous
#include <cuda_runtime.h>
#include <cuda_bf16.h>
#include <math.h>
#include <stdint.h>

#define BATCH   4096
#define SEQ     64
#define CDIM    256
#define HEADS   8
#define HDIM    32
#define NW      64
#define MROWS   (BATCH * SEQ)        // 262144
#define QKVDIM  768
#define GK      256

// Scratch (device globals)
__device__ float g_qkv[(size_t)MROWS * QKVDIM];          // f32 qkv
__device__ __nv_bfloat16 g_x_hi[(size_t)MROWS * CDIM];
__device__ __nv_bfloat16 g_x_mid[(size_t)MROWS * CDIM];
__device__ __nv_bfloat16 g_att_hi[(size_t)MROWS * CDIM];
__device__ __nv_bfloat16 g_att_mid[(size_t)MROWS * CDIM];
__device__ __nv_bfloat16 g_wq_hi[QKVDIM * GK];
__device__ __nv_bfloat16 g_wq_mid[QKVDIM * GK];
__device__ __nv_bfloat16 g_wp_hi[CDIM * GK];
__device__ __nv_bfloat16 g_wp_mid[CDIM * GK];
__device__ float g_rope_cos[SEQ * 16];
__device__ float g_rope_sin[SEQ * 16];

#define SW128(b) ((b) ^ (((b) >> 3) & 0x70))

__device__ __forceinline__ uint32_t smem_u32(const void* p) {
    uint32_t a;
    asm("{ .reg .u64 t; cvta.to.shared.u64 t, %1; cvt.u32.u64 %0, t; }"
        : "=r"(a) : "l"(p));
    return a;
}
__device__ __forceinline__ void ldmatrix_x4(uint32_t* r, uint32_t addr) {
    asm volatile("ldmatrix.sync.aligned.m8n8.x4.shared.b16 {%0,%1,%2,%3}, [%4];"
                 : "=r"(r[0]), "=r"(r[1]), "=r"(r[2]), "=r"(r[3]) : "r"(addr));
}
__device__ __forceinline__ void mma_bf16(float* c, const uint32_t* a,
                                         const uint32_t* b) {
    asm volatile(
        "mma.sync.aligned.m16n8k16.row.col.f32.bf16.bf16.f32 "
        "{%0,%1,%2,%3}, {%4,%5,%6,%7}, {%8,%9}, {%0,%1,%2,%3};"
        : "+f"(c[0]), "+f"(c[1]), "+f"(c[2]), "+f"(c[3])
        : "r"(a[0]), "r"(a[1]), "r"(a[2]), "r"(a[3]), "r"(b[0]), "r"(b[1]));
}
__device__ __forceinline__ void cp16(uint32_t dst, const void* src) {
    asm volatile("cp.async.cg.shared.global [%0], [%1], 16;"
                 :: "r"(dst), "l"(src));
}
#define CP_COMMIT() asm volatile("cp.async.commit_group;" ::: "memory")
#define CP_WAIT(n)  asm volatile("cp.async.wait_group %0;" :: "n"(n) : "memory")

__device__ __forceinline__ uint32_t pack_bf2(__nv_bfloat16 a, __nv_bfloat16 b) {
    return (uint32_t)__bfloat16_as_ushort(a) |
           ((uint32_t)__bfloat16_as_ushort(b) << 16);
}
// split two f32 into hi/mid bf16x2 regs
__device__ __forceinline__ void split2(float a, float b, uint32_t& hi, uint32_t& mid) {
    __nv_bfloat16 ha = __float2bfloat16(a);
    __nv_bfloat16 hb = __float2bfloat16(b);
    __nv_bfloat16 ma = __float2bfloat16(a - __bfloat162float(ha));
    __nv_bfloat16 mb = __float2bfloat16(b - __bfloat162float(hb));
    hi  = pack_bf2(ha, hb);
    mid = pack_bf2(ma, mb);
}

// ===========================================================================
// f32 -> (hi, mid) bf16 split, float4 granular
// ===========================================================================
__global__ void __launch_bounds__(256)
split_kernel(const float* __restrict__ src,
             __nv_bfloat16* __restrict__ hi,
             __nv_bfloat16* __restrict__ mid, int n4)
{
    int i = blockIdx.x * 256 + threadIdx.x;
    if (i >= n4) return;
    float4 v = *(const float4*)&src[(size_t)i * 4];
    uint32_t h0, m0, h1, m1;
    split2(v.x, v.y, h0, m0);
    split2(v.z, v.w, h1, m1);
    uint2 hv = make_uint2(h0, h1);
    uint2 mv = make_uint2(m0, m1);
    *(uint2*)&hi[(size_t)i * 4]  = hv;
    *(uint2*)&mid[(size_t)i * 4] = mv;
}

// ===========================================================================
// Pipelined bf16 GEMM: C[M,N] = A @ W^T + bias (A,W pre-split hi/mid)
// BM=128 BN=64 KC=64, 2-stage cp.async double buffer, 256 thr
// ===========================================================================
#define KC       64
#define S_AHI    0
#define S_AMID   16384
#define S_BHI    32768
#define S_BMID   40960
#define STAGE_BYTES 49152
#define SMEM_GEMM_BYTES (2 * STAGE_BYTES)   // 98304

__device__ __forceinline__ void gemm_prefetch(
    uint32_t sb, int stage,
    const __nv_bfloat16* Ahi, const __nv_bfloat16* Amid,
    const __nv_bfloat16* Whi, const __nv_bfloat16* Wmid,
    int k0, int tid)
{
    uint32_t base = sb + stage * STAGE_BYTES;
#pragma unroll
    for (int i = 0; i < 4; i++) {
        int idx = i * 256 + tid;
        int r   = idx >> 3;
        int c16 = idx & 7;
        uint32_t d = SW128((uint32_t)(r * 128 + c16 * 16));
        const __nv_bfloat16* sh = Ahi  + (size_t)r * GK + k0 + c16 * 8;
        const __nv_bfloat16* sm = Amid + (size_t)r * GK + k0 + c16 * 8;
        cp16(base + S_AHI  + d, sh);
        cp16(base + S_AMID + d, sm);
    }
#pragma unroll
    for (int i = 0; i < 2; i++) {
        int idx = i * 256 + tid;
        int r   = idx >> 3;
        int c16 = idx & 7;
        uint32_t d = SW128((uint32_t)(r * 128 + c16 * 16));
        const __nv_bfloat16* sh = Whi  + (size_t)r * GK + k0 + c16 * 8;
        const __nv_bfloat16* sm = Wmid + (size_t)r * GK + k0 + c16 * 8;
        cp16(base + S_BHI  + d, sh);
        cp16(base + S_BMID + d, sm);
    }
}

__global__ void __launch_bounds__(256, 2)
gemm_bf16_kernel(const __nv_bfloat16* __restrict__ Ahi,
                 const __nv_bfloat16* __restrict__ Amid,
                 const __nv_bfloat16* __restrict__ Whi,
                 const __nv_bfloat16* __restrict__ Wmid,
                 const float* __restrict__ bias,
                 float* __restrict__ C,
                 int Ncols)
{
    extern __shared__ char smem[];
    const uint32_t sb = smem_u32(smem);
    const int tid  = threadIdx.x;
    const int wid  = tid >> 5;
    const int lane = tid & 31;
    const int wm   = wid & 3;
    const int wn   = wid >> 2;
    const int row0 = blockIdx.y * 128;
    const int col0 = blockIdx.x * 64;

    const __nv_bfloat16* Ah = Ahi  + (size_t)row0 * GK;
    const __nv_bfloat16* Am = Amid + (size_t)row0 * GK;
    const __nv_bfloat16* Wh = Whi  + (size_t)col0 * GK;
    const __nv_bfloat16* Wm = Wmid + (size_t)col0 * GK;

    float acc[2][4][4];
#pragma unroll
    for (int mt = 0; mt < 2; mt++)
#pragma unroll
        for (int nt = 0; nt < 4; nt++)
#pragma unroll
            for (int e = 0; e < 4; e++) acc[mt][nt][e] = 0.f;

    const int arow  = wm * 32 + (lane & 15);
    const int acol8 = (lane >> 4) * 8;
    const int bn_lo = wn * 32 + ((lane >> 4) << 3) + (lane & 7);
    const int bc8   = ((lane >> 3) & 1) << 3;

    gemm_prefetch(sb, 0, Ah, Am, Wh, Wm, 0, tid);
    CP_COMMIT();

    const int NC = GK / KC;   // 4
#pragma unroll
    for (int c = 0; c < NC; c++) {
        if (c + 1 < NC) {
            gemm_prefetch(sb, (c + 1) & 1, Ah, Am, Wh, Wm, (c + 1) * KC, tid);
            CP_COMMIT();
            CP_WAIT(1);
        } else {
            CP_WAIT(0);
        }
        __syncthreads();

        uint32_t base = sb + (c & 1) * STAGE_BYTES;
#pragma unroll
        for (int ks = 0; ks < 4; ks++) {
            uint32_t ah[2][4], am[2][4], bh[2][4], bm[2][4];
            const int kcA = ks * 16 + acol8;
#pragma unroll
            for (int mt = 0; mt < 2; mt++) {
                uint32_t off = SW128((uint32_t)((arow + mt * 16) * 128 + kcA * 2));
                ldmatrix_x4(ah[mt], base + S_AHI  + off);
                ldmatrix_x4(am[mt], base + S_AMID + off);
            }
            const int kcB = ks * 16 + bc8;
#pragma unroll
            for (int pp = 0; pp < 2; pp++) {
                uint32_t off = SW128((uint32_t)((bn_lo + pp * 16) * 128 + kcB * 2));
                ldmatrix_x4(bh[pp], base + S_BHI  + off);
                ldmatrix_x4(bm[pp], base + S_BMID + off);
            }
#pragma unroll
            for (int mt = 0; mt < 2; mt++)
#pragma unroll
                for (int nt = 0; nt < 4; nt++) {
                    const uint32_t* bhp = &bh[nt >> 1][(nt & 1) * 2];
                    const uint32_t* bmp = &bm[nt >> 1][(nt & 1) * 2];
                    mma_bf16(acc[mt][nt], ah[mt], bhp);
                    mma_bf16(acc[mt][nt], ah[mt], bmp);
                    mma_bf16(acc[mt][nt], am[mt], bhp);
                }
        }
        __syncthreads();
    }

#pragma unroll
    for (int mt = 0; mt < 2; mt++) {
        int r_ = row0 + wm * 32 + mt * 16 + (lane >> 2);
#pragma unroll
        for (int nt = 0; nt < 4; nt++) {
            int c_ = col0 + wn * 32 + nt * 8 + (lane & 3) * 2;
            float2 bv = *(const float2*)&bias[c_];
            float2 o0, o1;
            o0.x = acc[mt][nt][0] + bv.x;
            o0.y = acc[mt][nt][1] + bv.y;
            o1.x = acc[mt][nt][2] + bv.x;
            o1.y = acc[mt][nt][3] + bv.y;
            *(float2*)&C[(size_t)r_ * Ncols + c_]       = o0;
            *(float2*)&C[(size_t)(r_ + 8) * Ncols + c_] = o1;
        }
    }
}

// ---------------------------------------------------------------------------
// RoPE table init
// ---------------------------------------------------------------------------
__global__ void rope_init_kernel()
{
    int i = threadIdx.x;            // 0..1023
    int n = i >> 4;
    int f = i & 15;
    const float NEG_LN1E4_OVER16 = -0.57564627324851142f;
    float inv = expf((float)f * NEG_LN1E4_OVER16);
    float t = (float)n + 0.1f;
    float s, c;
    sincosf(t * inv, &s, &c);
    g_rope_cos[i] = c;
    g_rope_sin[i] = s;
}

// ===========================================================================
// Tensor-core attention: one CTA per (b,h), 128 threads (4 warps).
// RoPE+norm -> bf16 split tiles -> QK^T (mma) -> softmax -> PV (mma)
// Writes hi/mid-split output for the proj GEMM.
// ===========================================================================
#define QK_STRIDE 80     // 64 bf16 cols max 32*2=64B + 16B pad
#define VT_STRIDE 144    // 64 j cols * 2B = 128B + 16B pad

__global__ void __launch_bounds__(128)
attn_mma_kernel(const float* __restrict__ mask,
                const float* __restrict__ logit_scale)
{
    __shared__ __align__(16) uint8_t qhi [SEQ * QK_STRIDE];
    __shared__ __align__(16) uint8_t qmid[SEQ * QK_STRIDE];
    __shared__ __align__(16) uint8_t khi [SEQ * QK_STRIDE];
    __shared__ __align__(16) uint8_t kmid[SEQ * QK_STRIDE];
    __shared__ __align__(16) uint8_t vthi [HDIM * VT_STRIDE];
    __shared__ __align__(16) uint8_t vtmid[HDIM * VT_STRIDE];

    const int b = blockIdx.x;
    const int h = blockIdx.y;
    const int tid  = threadIdx.x;
    const int lane = tid & 31;
    const int warp = tid >> 5;

    // ---- phase 1: load, RoPE+normalize q/k, split-convert, store tiles ----
    {
        const int j    = tid >> 1;
        const int half = tid & 1;
        const int db   = half * 16;
        const float* src = g_qkv + ((size_t)(b * SEQ + j)) * QKVDIM + h * HDIM + db;

        float cs[16], sn[16];
#pragma unroll
        for (int i = 0; i < 16; i++) {
            cs[i] = g_rope_cos[j * 16 + i];
            sn[i] = g_rope_sin[j * 16 + i];
        }
        const float sgn = half ? 1.f : -1.f;

#pragma unroll
        for (int qk = 0; qk < 2; qk++) {     // 0 = q, 1 = k
            float x[16];
#pragma unroll
            for (int v4 = 0; v4 < 4; v4++)
                *(float4*)&x[v4 * 4] = *(const float4*)&src[qk * 256 + v4 * 4];
            float y[16];
            float ss = 0.f;
#pragma unroll
            for (int i = 0; i < 16; i++) {
                float other = __shfl_xor_sync(0xffffffffu, x[i], 1);
                y[i] = x[i] * cs[i] + sgn * other * sn[i];
                ss += y[i] * y[i];
            }
            ss += __shfl_xor_sync(0xffffffffu, ss, 1);
            float inv = rsqrtf(fmaxf(ss, 1e-24f));
            uint32_t hiw[8], miw[8];
#pragma unroll
            for (int i = 0; i < 8; i++)
                split2(y[2 * i] * inv, y[2 * i + 1] * inv, hiw[i], miw[i]);
            uint8_t* dsth = (qk ? khi  : qhi)  + j * QK_STRIDE + db * 2;
            uint8_t* dstm = (qk ? kmid : qmid) + j * QK_STRIDE + db * 2;
            *(uint4*)(dsth)      = make_uint4(hiw[0], hiw[1], hiw[2], hiw[3]);
            *(uint4*)(dsth + 16) = make_uint4(hiw[4], hiw[5], hiw[6], hiw[7]);
            *(uint4*)(dstm)      = make_uint4(miw[0], miw[1], miw[2], miw[3]);
            *(uint4*)(dstm + 16) = make_uint4(miw[4], miw[5], miw[6], miw[7]);
        }
        // v: no rope, store transposed
        float xv[16];
#pragma unroll
        for (int v4 = 0; v4 < 4; v4++)
            *(float4*)&xv[v4 * 4] = *(const float4*)&src[512 + v4 * 4];
#pragma unroll
        for (int i = 0; i < 16; i++) {
            __nv_bfloat16 hv = __float2bfloat16(xv[i]);
            __nv_bfloat16 mv = __float2bfloat16(xv[i] - __bfloat162float(hv));
            int d = db + i;
            *(uint16_t*)(vthi  + d * VT_STRIDE + j * 2) = __bfloat16_as_ushort(hv);
            *(uint16_t*)(vtmid + d * VT_STRIDE + j * 2) = __bfloat16_as_ushort(mv);
        }
    }
    __syncthreads();

    // ---- phase 2: scores = Qn Kn^T (hi/mid split) ----
    const int m0  = warp * 16;
    const int ar  = lane & 15;
    const int ac8 = (lane >> 4) * 8;
    const int bnp = ((lane >> 4) << 3) + (lane & 7);
    const int bc8 = ((lane >> 3) & 1) << 3;

    uint32_t ah[2][4], am[2][4];
#pragma unroll
    for (int kt = 0; kt < 2; kt++) {
        uint32_t off = (uint32_t)((m0 + ar) * QK_STRIDE + (kt * 16 + ac8) * 2);
        ldmatrix_x4(ah[kt], smem_u32(qhi)  + off);
        ldmatrix_x4(am[kt], smem_u32(qmid) + off);
    }

    float acc[8][4];
#pragma unroll
    for (int nt = 0; nt < 8; nt++)
#pragma unroll
        for (int e = 0; e < 4; e++) acc[nt][e] = 0.f;

#pragma unroll
    for (int pp = 0; pp < 4; pp++) {
        uint32_t bh[2][4], bm[2][4];
#pragma unroll
        for (int kt = 0; kt < 2; kt++) {
            uint32_t off = (uint32_t)((pp * 16 + bnp) * QK_STRIDE + (kt * 16 + bc8) * 2);
            ldmatrix_x4(bh[kt], smem_u32(khi)  + off);
            ldmatrix_x4(bm[kt], smem_u32(kmid) + off);
        }
#pragma unroll
        for (int kt = 0; kt < 2; kt++)
#pragma unroll
            for (int n2 = 0; n2 < 2; n2++) {
                float* a = acc[pp * 2 + n2];
                mma_bf16(a, ah[kt], &bh[kt][n2 * 2]);
                mma_bf16(a, ah[kt], &bm[kt][n2 * 2]);
                mma_bf16(a, am[kt], &bh[kt][n2 * 2]);
            }
    }

    // ---- softmax (normalization deferred) ----
    const float MAX_LOGIT = 4.6051701859880914f;
    const float scale = __expf(fminf(logit_scale[h], MAX_LOGIT));
    const float* mrow = mask + (size_t)(b & (NW - 1)) * SEQ * SEQ;
    const int r0 = m0 + (lane >> 2);
    const int r1 = r0 + 8;
    const int coff = (lane & 3) * 2;

    float mx0 = -1e30f, mx1 = -1e30f;
#pragma unroll
    for (int nt = 0; nt < 8; nt++) {
        int cc = nt * 8 + coff;
        float2 ma = *(const float2*)&mrow[r0 * SEQ + cc];
        float2 mb = *(const float2*)&mrow[r1 * SEQ + cc];
        acc[nt][0] = fmaf(acc[nt][0], scale, ma.x);
        acc[nt][1] = fmaf(acc[nt][1], scale, ma.y);
        acc[nt][2] = fmaf(acc[nt][2], scale, mb.x);
        acc[nt][3] = fmaf(acc[nt][3], scale, mb.y);
        mx0 = fmaxf(mx0, fmaxf(acc[nt][0], acc[nt][1]));
        mx1 = fmaxf(mx1, fmaxf(acc[nt][2], acc[nt][3]));
    }
    mx0 = fmaxf(mx0, __shfl_xor_sync(0xffffffffu, mx0, 1));
    mx0 = fmaxf(mx0, __shfl_xor_sync(0xffffffffu, mx0, 2));
    mx1 = fmaxf(mx1, __shfl_xor_sync(0xffffffffu, mx1, 1));
    mx1 = fmaxf(mx1, __shfl_xor_sync(0xffffffffu, mx1, 2));

    float sum0 = 0.f, sum1 = 0.f;
#pragma unroll
    for (int nt = 0; nt < 8; nt++) {
        acc[nt][0] = __expf(acc[nt][0] - mx0);
        acc[nt][1] = __expf(acc[nt][1] - mx0);
        acc[nt][2] = __expf(acc[nt][2] - mx1);
        acc[nt][3] = __expf(acc[nt][3] - mx1);
        sum0 += acc[nt][0] + acc[nt][1];
        sum1 += acc[nt][2] + acc[nt][3];
    }
    sum0 += __shfl_xor_sync(0xffffffffu, sum0, 1);
    sum0 += __shfl_xor_sync(0xffffffffu, sum0, 2);
    sum1 += __shfl_xor_sync(0xffffffffu, sum1, 1);
    sum1 += __shfl_xor_sync(0xffffffffu, sum1, 2);

    // ---- PV: O = P V (P from score fragments, hi/mid split) ----
    float oacc[4][4];
#pragma unroll
    for (int dt = 0; dt < 4; dt++)
#pragma unroll
        for (int e = 0; e < 4; e++) oacc[dt][e] = 0.f;

#pragma unroll
    for (int kt = 0; kt < 4; kt++) {
        uint32_t phi[4], pmi[4];
        split2(acc[2 * kt][0],     acc[2 * kt][1],     phi[0], pmi[0]);
        split2(acc[2 * kt][2],     acc[2 * kt][3],     phi[1], pmi[1]);
        split2(acc[2 * kt + 1][0], acc[2 * kt + 1][1], phi[2], pmi[2]);
        split2(acc[2 * kt + 1][2], acc[2 * kt + 1][3], phi[3], pmi[3]);

        uint32_t vh[2][4], vm[2][4];
#pragma unroll
        for (int d2 = 0; d2 < 2; d2++) {
            uint32_t off = (uint32_t)((d2 * 16 + bnp) * VT_STRIDE + (kt * 16 + bc8) * 2);
            ldmatrix_x4(vh[d2], smem_u32(vthi)  + off);
            ldmatrix_x4(vm[d2], smem_u32(vtmid) + off);
        }
#pragma unroll
        for (int dt = 0; dt < 4; dt++) {
            const uint32_t* bhp = &vh[dt >> 1][(dt & 1) * 2];
            const uint32_t* bmp = &vm[dt >> 1][(dt & 1) * 2];
            mma_bf16(oacc[dt], phi, bhp);
            mma_bf16(oacc[dt], phi, bmp);
            mma_bf16(oacc[dt], pmi, bhp);
        }
    }

    // ---- epilogue: normalize rows, split-store ----
    const float inv0 = 1.f / sum0;
    const float inv1 = 1.f / sum1;
#pragma unroll
    for (int dt = 0; dt < 4; dt++) {
        int col = dt * 8 + coff;
        size_t a0 = ((size_t)(b * SEQ + r0)) * CDIM + h * HDIM + col;
        size_t a1 = ((size_t)(b * SEQ + r1)) * CDIM + h * HDIM + col;
        uint32_t h0, m0w, h1, m1w;
        split2(oacc[dt][0] * inv0, oacc[dt][1] * inv0, h0, m0w);
        split2(oacc[dt][2] * inv1, oacc[dt][3] * inv1, h1, m1w);
        *(uint32_t*)&g_att_hi[a0]  = h0;
        *(uint32_t*)&g_att_mid[a0] = m0w;
        *(uint32_t*)&g_att_hi[a1]  = h1;
        *(uint32_t*)&g_att_mid[a1] = m1w;
    }
}

// ---------------------------------------------------------------------------
extern "C" void kernel_launch(void* const* d_in, const int* in_sizes, int n_in,
                              void* d_out, int out_size)
{
    const float* x           = (const float*)d_in[0];
    const float* mask        = (const float*)d_in[1];
    const float* qkv_w       = (const float*)d_in[2];
    const float* qkv_b       = (const float*)d_in[3];
    const float* proj_w      = (const float*)d_in[4];
    const float* proj_b      = (const float*)d_in[5];
    const float* logit_scale = (const float*)d_in[6];
    float* out = (float*)d_out;

    float* qkv_ptr = nullptr;
    __nv_bfloat16 *xh, *xm, *ah, *am, *wqh, *wqm, *wph, *wpm;
    cudaGetSymbolAddress((void**)&qkv_ptr, g_qkv);
    cudaGetSymbolAddress((void**)&xh,  g_x_hi);
    cudaGetSymbolAddress((void**)&xm,  g_x_mid);
    cudaGetSymbolAddress((void**)&ah,  g_att_hi);
    cudaGetSymbolAddress((void**)&am,  g_att_mid);
    cudaGetSymbolAddress((void**)&wqh, g_wq_hi);
    cudaGetSymbolAddress((void**)&wqm, g_wq_mid);
    cudaGetSymbolAddress((void**)&wph, g_wp_hi);
    cudaGetSymbolAddress((void**)&wpm, g_wp_mid);

    cudaFuncSetAttribute(gemm_bf16_kernel,
                         cudaFuncAttributeMaxDynamicSharedMemorySize,
                         SMEM_GEMM_BYTES);

    // 0) RoPE table + input splits
    rope_init_kernel<<<1, 1024>>>();
    split_kernel<<<(MROWS * CDIM / 4 + 255) / 256, 256>>>(x, xh, xm,
                                                          MROWS * CDIM / 4);
    split_kernel<<<(QKVDIM * GK / 4 + 255) / 256, 256>>>(qkv_w, wqh, wqm,
                                                         QKVDIM * GK / 4);
    split_kernel<<<(CDIM * GK / 4 + 255) / 256, 256>>>(proj_w, wph, wpm,
                                                       CDIM * GK / 4);

    // 1) QKV GEMM
    {
        dim3 grid(QKVDIM / 64, MROWS / 128);
        gemm_bf16_kernel<<<grid, 256, SMEM_GEMM_BYTES>>>(xh, xm, wqh, wqm,
                                                         qkv_b, qkv_ptr, QKVDIM);
    }
    // 2) Attention (tensor cores)
    {
        dim3 grid(BATCH, HEADS);
        attn_mma_kernel<<<grid, 128>>>(mask, logit_scale);
    }
    // 3) Proj GEMM
    {
        dim3 grid(CDIM / 64, MROWS / 128);
        gemm_bf16_kernel<<<grid, 256, SMEM_GEMM_BYTES>>>(ah, am, wph, wpm,
                                                         proj_b, out, CDIM);
    }
}

// round 5
// speedup vs baseline: 3.4007x; 1.5139x over previous
#include <cuda_runtime.h>
#include <cuda_fp16.h>
#include <math.h>
#include <stdint.h>

#define BATCH   4096
#define SEQ     64
#define CDIM    256
#define HEADS   8
#define HDIM    32
#define NW      64
#define MROWS   (BATCH * SEQ)        // 262144
#define QKVDIM  768
#define GK      256

// Scratch (device globals)
__device__ float g_qkv[(size_t)MROWS * QKVDIM];
__device__ __half g_x_hi[(size_t)MROWS * CDIM];
__device__ __half g_x_mid[(size_t)MROWS * CDIM];
__device__ __half g_att_hi[(size_t)MROWS * CDIM];
__device__ __half g_att_mid[(size_t)MROWS * CDIM];
__device__ __half g_wq_hi[QKVDIM * GK];
__device__ __half g_wq_mid[QKVDIM * GK];
__device__ __half g_wp_hi[CDIM * GK];
__device__ __half g_wp_mid[CDIM * GK];
__device__ float g_rope_cos[SEQ * 16];
__device__ float g_rope_sin[SEQ * 16];

#define SW128(b) ((b) ^ (((b) >> 3) & 0x70))

__device__ __forceinline__ uint32_t smem_u32(const void* p) {
    uint32_t a;
    asm("{ .reg .u64 t; cvta.to.shared.u64 t, %1; cvt.u32.u64 %0, t; }"
        : "=r"(a) : "l"(p));
    return a;
}
__device__ __forceinline__ void ldmatrix_x4(uint32_t* r, uint32_t addr) {
    asm volatile("ldmatrix.sync.aligned.m8n8.x4.shared.b16 {%0,%1,%2,%3}, [%4];"
                 : "=r"(r[0]), "=r"(r[1]), "=r"(r[2]), "=r"(r[3]) : "r"(addr));
}
// fp16 inputs, f32 accumulate
__device__ __forceinline__ void mma_f32acc(float* c, const uint32_t* a,
                                           const uint32_t* b) {
    asm volatile(
        "mma.sync.aligned.m16n8k16.row.col.f32.f16.f16.f32 "
        "{%0,%1,%2,%3}, {%4,%5,%6,%7}, {%8,%9}, {%0,%1,%2,%3};"
        : "+f"(c[0]), "+f"(c[1]), "+f"(c[2]), "+f"(c[3])
        : "r"(a[0]), "r"(a[1]), "r"(a[2]), "r"(a[3]), "r"(b[0]), "r"(b[1]));
}
// fp16 inputs, f16 accumulate (2x issue rate hoped)
__device__ __forceinline__ void mma_f16acc(uint32_t* c, const uint32_t* a,
                                           const uint32_t* b) {
    asm volatile(
        "mma.sync.aligned.m16n8k16.row.col.f16.f16.f16.f16 "
        "{%0,%1}, {%2,%3,%4,%5}, {%6,%7}, {%0,%1};"
        : "+r"(c[0]), "+r"(c[1])
        : "r"(a[0]), "r"(a[1]), "r"(a[2]), "r"(a[3]), "r"(b[0]), "r"(b[1]));
}
__device__ __forceinline__ void cp16(uint32_t dst, const void* src) {
    asm volatile("cp.async.cg.shared.global [%0], [%1], 16;"
                 :: "r"(dst), "l"(src));
}
#define CP_COMMIT() asm volatile("cp.async.commit_group;" ::: "memory")
#define CP_WAIT(n)  asm volatile("cp.async.wait_group %0;" :: "n"(n) : "memory")

// split two f32 into (hi, mid) f16x2 regs
__device__ __forceinline__ void split2h(float a, float b,
                                        uint32_t& hi, uint32_t& mid) {
    __half ha = __float2half_rn(a);
    __half hb = __float2half_rn(b);
    __half2 hp = __halves2half2(ha, hb);
    hi = *(uint32_t*)&hp;
    __half2 mp = __floats2half2_rn(a - __half2float(ha), b - __half2float(hb));
    mid = *(uint32_t*)&mp;
}
__device__ __forceinline__ uint32_t pack_h2(float a, float b) {
    __half2 hp = __floats2half2_rn(a, b);
    return *(uint32_t*)&hp;
}
__device__ __forceinline__ float2 unpack_h2(uint32_t v) {
    return __half22float2(*(__half2*)&v);
}

// ===========================================================================
// f32 -> (hi, mid) fp16 split
// ===========================================================================
__global__ void __launch_bounds__(256)
split_kernel(const float* __restrict__ src,
             __half* __restrict__ hi,
             __half* __restrict__ mid, int n4)
{
    int i = blockIdx.x * 256 + threadIdx.x;
    if (i >= n4) return;
    float4 v = *(const float4*)&src[(size_t)i * 4];
    uint32_t h0, m0, h1, m1;
    split2h(v.x, v.y, h0, m0);
    split2h(v.z, v.w, h1, m1);
    *(uint2*)&hi[(size_t)i * 4]  = make_uint2(h0, h1);
    *(uint2*)&mid[(size_t)i * 4] = make_uint2(m0, m1);
}

// ===========================================================================
// Pipelined fp16-split GEMM, mixed-precision accumulation
// BM=128 BN=64 KC=64, 2-stage cp.async, 256 threads
// ===========================================================================
#define KC       64
#define S_AHI    0
#define S_AMID   16384
#define S_BHI    32768
#define S_BMID   40960
#define STAGE_BYTES 49152
#define SMEM_GEMM_BYTES (2 * STAGE_BYTES)   // 98304

__device__ __forceinline__ void gemm_prefetch(
    uint32_t sb, int stage,
    const __half* Ahi, const __half* Amid,
    const __half* Whi, const __half* Wmid,
    int k0, int tid)
{
    uint32_t base = sb + stage * STAGE_BYTES;
#pragma unroll
    for (int i = 0; i < 4; i++) {
        int idx = i * 256 + tid;
        int r   = idx >> 3;
        int c16 = idx & 7;
        uint32_t d = SW128((uint32_t)(r * 128 + c16 * 16));
        cp16(base + S_AHI  + d, Ahi  + (size_t)r * GK + k0 + c16 * 8);
        cp16(base + S_AMID + d, Amid + (size_t)r * GK + k0 + c16 * 8);
    }
#pragma unroll
    for (int i = 0; i < 2; i++) {
        int idx = i * 256 + tid;
        int r   = idx >> 3;
        int c16 = idx & 7;
        uint32_t d = SW128((uint32_t)(r * 128 + c16 * 16));
        cp16(base + S_BHI  + d, Whi  + (size_t)r * GK + k0 + c16 * 8);
        cp16(base + S_BMID + d, Wmid + (size_t)r * GK + k0 + c16 * 8);
    }
}

__global__ void __launch_bounds__(256, 2)
gemm_f16_kernel(const __half* __restrict__ Ahi,
                const __half* __restrict__ Amid,
                const __half* __restrict__ Whi,
                const __half* __restrict__ Wmid,
                const float* __restrict__ bias,
                float* __restrict__ C,
                int Ncols)
{
    extern __shared__ char smem[];
    const uint32_t sb = smem_u32(smem);
    const int tid  = threadIdx.x;
    const int wid  = tid >> 5;
    const int lane = tid & 31;
    const int wm   = wid & 3;
    const int wn   = wid >> 2;
    const int row0 = blockIdx.y * 128;
    const int col0 = blockIdx.x * 64;

    const __half* Ah = Ahi  + (size_t)row0 * GK;
    const __half* Am = Amid + (size_t)row0 * GK;
    const __half* Wh = Whi  + (size_t)col0 * GK;
    const __half* Wm = Wmid + (size_t)col0 * GK;

    float acc[2][4][4];
    uint32_t hacc[2][4][2];
#pragma unroll
    for (int mt = 0; mt < 2; mt++)
#pragma unroll
        for (int nt = 0; nt < 4; nt++) {
#pragma unroll
            for (int e = 0; e < 4; e++) acc[mt][nt][e] = 0.f;
            hacc[mt][nt][0] = 0u; hacc[mt][nt][1] = 0u;
        }

    const int arow  = wm * 32 + (lane & 15);
    const int acol8 = (lane >> 4) * 8;
    const int bn_lo = wn * 32 + ((lane >> 4) << 3) + (lane & 7);
    const int bc8   = ((lane >> 3) & 1) << 3;

    gemm_prefetch(sb, 0, Ah, Am, Wh, Wm, 0, tid);
    CP_COMMIT();

    const int NC = GK / KC;   // 4
#pragma unroll
    for (int c = 0; c < NC; c++) {
        if (c + 1 < NC) {
            gemm_prefetch(sb, (c + 1) & 1, Ah, Am, Wh, Wm, (c + 1) * KC, tid);
            CP_COMMIT();
            CP_WAIT(1);
        } else {
            CP_WAIT(0);
        }
        __syncthreads();

        uint32_t base = sb + (c & 1) * STAGE_BYTES;
#pragma unroll
        for (int ks = 0; ks < 4; ks++) {
            uint32_t ah[2][4], am[2][4], bh[2][4], bm[2][4];
            const int kcA = ks * 16 + acol8;
#pragma unroll
            for (int mt = 0; mt < 2; mt++) {
                uint32_t off = SW128((uint32_t)((arow + mt * 16) * 128 + kcA * 2));
                ldmatrix_x4(ah[mt], base + S_AHI  + off);
                ldmatrix_x4(am[mt], base + S_AMID + off);
            }
            const int kcB = ks * 16 + bc8;
#pragma unroll
            for (int pp = 0; pp < 2; pp++) {
                uint32_t off = SW128((uint32_t)((bn_lo + pp * 16) * 128 + kcB * 2));
                ldmatrix_x4(bh[pp], base + S_BHI  + off);
                ldmatrix_x4(bm[pp], base + S_BMID + off);
            }
#pragma unroll
            for (int mt = 0; mt < 2; mt++)
#pragma unroll
                for (int nt = 0; nt < 4; nt++) {
                    const uint32_t* bhp = &bh[nt >> 1][(nt & 1) * 2];
                    const uint32_t* bmp = &bm[nt >> 1][(nt & 1) * 2];
                    mma_f32acc(acc[mt][nt], ah[mt], bhp);   // hi*hi -> f32
                    mma_f16acc(hacc[mt][nt], ah[mt], bmp);  // hi*mid -> f16
                    mma_f16acc(hacc[mt][nt], am[mt], bhp);  // mid*hi -> f16
                }
        }
        __syncthreads();
    }

#pragma unroll
    for (int mt = 0; mt < 2; mt++) {
        int r_ = row0 + wm * 32 + mt * 16 + (lane >> 2);
#pragma unroll
        for (int nt = 0; nt < 4; nt++) {
            int c_ = col0 + wn * 32 + nt * 8 + (lane & 3) * 2;
            float2 bv = *(const float2*)&bias[c_];
            float2 cl = unpack_h2(hacc[mt][nt][0]);
            float2 ch = unpack_h2(hacc[mt][nt][1]);
            float2 o0, o1;
            o0.x = acc[mt][nt][0] + cl.x + bv.x;
            o0.y = acc[mt][nt][1] + cl.y + bv.y;
            o1.x = acc[mt][nt][2] + ch.x + bv.x;
            o1.y = acc[mt][nt][3] + ch.y + bv.y;
            *(float2*)&C[(size_t)r_ * Ncols + c_]       = o0;
            *(float2*)&C[(size_t)(r_ + 8) * Ncols + c_] = o1;
        }
    }
}

// ---------------------------------------------------------------------------
__global__ void rope_init_kernel()
{
    int i = threadIdx.x;            // 0..1023
    int n = i >> 4;
    int f = i & 15;
    const float NEG_LN1E4_OVER16 = -0.57564627324851142f;
    float inv = expf((float)f * NEG_LN1E4_OVER16);
    float t = (float)n + 0.1f;
    float s, c;
    sincosf(t * inv, &s, &c);
    g_rope_cos[i] = c;
    g_rope_sin[i] = s;
}

// ===========================================================================
// Tensor-core attention (fp16): one CTA per (b,h), 128 threads.
// QK^T: hi*hi f32acc + 2 corrections f16acc. PV: P(fp16) x V(hi+mid), 2 MMAs.
// ===========================================================================
#define QK_STRIDE 80
#define VT_STRIDE 144

__global__ void __launch_bounds__(128)
attn_mma_kernel(const float* __restrict__ mask,
                const float* __restrict__ logit_scale)
{
    __shared__ __align__(16) uint8_t qhi [SEQ * QK_STRIDE];
    __shared__ __align__(16) uint8_t qmid[SEQ * QK_STRIDE];
    __shared__ __align__(16) uint8_t khi [SEQ * QK_STRIDE];
    __shared__ __align__(16) uint8_t kmid[SEQ * QK_STRIDE];
    __shared__ __align__(16) uint8_t vthi [HDIM * VT_STRIDE];
    __shared__ __align__(16) uint8_t vtmid[HDIM * VT_STRIDE];

    const int b = blockIdx.x;
    const int h = blockIdx.y;
    const int tid  = threadIdx.x;
    const int lane = tid & 31;
    const int warp = tid >> 5;

    // ---- phase 1: load, RoPE+normalize(+scale) q/k, fp16 split tiles ----
    {
        const int j    = tid >> 1;
        const int half = tid & 1;
        const int db   = half * 16;
        const float* src = g_qkv + ((size_t)(b * SEQ + j)) * QKVDIM + h * HDIM + db;
        const float MAX_LOGIT = 4.6051701859880914f;
        const float scale = __expf(fminf(logit_scale[h], MAX_LOGIT));

        float cs[16], sn[16];
#pragma unroll
        for (int i = 0; i < 16; i++) {
            cs[i] = g_rope_cos[j * 16 + i];
            sn[i] = g_rope_sin[j * 16 + i];
        }
        const float sgn = half ? 1.f : -1.f;

#pragma unroll
        for (int qk = 0; qk < 2; qk++) {
            float x[16];
#pragma unroll
            for (int v4 = 0; v4 < 4; v4++)
                *(float4*)&x[v4 * 4] = *(const float4*)&src[qk * 256 + v4 * 4];
            float y[16];
            float ss = 0.f;
#pragma unroll
            for (int i = 0; i < 16; i++) {
                float other = __shfl_xor_sync(0xffffffffu, x[i], 1);
                y[i] = x[i] * cs[i] + sgn * other * sn[i];
                ss += y[i] * y[i];
            }
            ss += __shfl_xor_sync(0xffffffffu, ss, 1);
            float inv = rsqrtf(fmaxf(ss, 1e-24f));
            if (qk == 0) inv *= scale;       // fold logit scale into q
            uint32_t hiw[8], miw[8];
#pragma unroll
            for (int i = 0; i < 8; i++)
                split2h(y[2 * i] * inv, y[2 * i + 1] * inv, hiw[i], miw[i]);
            uint8_t* dsth = (qk ? khi  : qhi)  + j * QK_STRIDE + db * 2;
            uint8_t* dstm = (qk ? kmid : qmid) + j * QK_STRIDE + db * 2;
            *(uint4*)(dsth)      = make_uint4(hiw[0], hiw[1], hiw[2], hiw[3]);
            *(uint4*)(dsth + 16) = make_uint4(hiw[4], hiw[5], hiw[6], hiw[7]);
            *(uint4*)(dstm)      = make_uint4(miw[0], miw[1], miw[2], miw[3]);
            *(uint4*)(dstm + 16) = make_uint4(miw[4], miw[5], miw[6], miw[7]);
        }
        // v: no rope; fp16 split, transposed store
        float xv[16];
#pragma unroll
        for (int v4 = 0; v4 < 4; v4++)
            *(float4*)&xv[v4 * 4] = *(const float4*)&src[512 + v4 * 4];
#pragma unroll
        for (int i = 0; i < 16; i++) {
            __half hv = __float2half_rn(xv[i]);
            __half mv = __float2half_rn(xv[i] - __half2float(hv));
            int d = db + i;
            *(uint16_t*)(vthi  + d * VT_STRIDE + j * 2) = __half_as_ushort(hv);
            *(uint16_t*)(vtmid + d * VT_STRIDE + j * 2) = __half_as_ushort(mv);
        }
    }
    __syncthreads();

    // ---- mask prefetch (hidden under QK MMAs by scheduler) ----
    const float* mrow = mask + (size_t)(b & (NW - 1)) * SEQ * SEQ;
    const int m0   = warp * 16;
    const int r0   = m0 + (lane >> 2);
    const int r1   = r0 + 8;
    const int coff = (lane & 3) * 2;
    float2 mA[8], mB[8];
#pragma unroll
    for (int nt = 0; nt < 8; nt++) {
        mA[nt] = *(const float2*)&mrow[r0 * SEQ + nt * 8 + coff];
        mB[nt] = *(const float2*)&mrow[r1 * SEQ + nt * 8 + coff];
    }

    // ---- QK^T ----
    const int ar  = lane & 15;
    const int ac8 = (lane >> 4) * 8;
    const int bnp = ((lane >> 4) << 3) + (lane & 7);
    const int bc8 = ((lane >> 3) & 1) << 3;

    uint32_t ah[2][4], am[2][4];
#pragma unroll
    for (int kt = 0; kt < 2; kt++) {
        uint32_t off = (uint32_t)((m0 + ar) * QK_STRIDE + (kt * 16 + ac8) * 2);
        ldmatrix_x4(ah[kt], smem_u32(qhi)  + off);
        ldmatrix_x4(am[kt], smem_u32(qmid) + off);
    }

    float acc[8][4];
    uint32_t hqk[8][2];
#pragma unroll
    for (int nt = 0; nt < 8; nt++) {
#pragma unroll
        for (int e = 0; e < 4; e++) acc[nt][e] = 0.f;
        hqk[nt][0] = 0u; hqk[nt][1] = 0u;
    }

#pragma unroll
    for (int pp = 0; pp < 4; pp++) {
        uint32_t bh[2][4], bm[2][4];
#pragma unroll
        for (int kt = 0; kt < 2; kt++) {
            uint32_t off = (uint32_t)((pp * 16 + bnp) * QK_STRIDE + (kt * 16 + bc8) * 2);
            ldmatrix_x4(bh[kt], smem_u32(khi)  + off);
            ldmatrix_x4(bm[kt], smem_u32(kmid) + off);
        }
#pragma unroll
        for (int kt = 0; kt < 2; kt++)
#pragma unroll
            for (int n2 = 0; n2 < 2; n2++) {
                int nt = pp * 2 + n2;
                mma_f32acc(acc[nt], ah[kt], &bh[kt][n2 * 2]);
                mma_f16acc(hqk[nt], ah[kt], &bm[kt][n2 * 2]);
                mma_f16acc(hqk[nt], am[kt], &bh[kt][n2 * 2]);
            }
    }

    // ---- softmax (deferred normalization) ----
    float mx0 = -1e30f, mx1 = -1e30f;
#pragma unroll
    for (int nt = 0; nt < 8; nt++) {
        float2 cl = unpack_h2(hqk[nt][0]);
        float2 ch = unpack_h2(hqk[nt][1]);
        acc[nt][0] += cl.x + mA[nt].x;
        acc[nt][1] += cl.y + mA[nt].y;
        acc[nt][2] += ch.x + mB[nt].x;
        acc[nt][3] += ch.y + mB[nt].y;
        mx0 = fmaxf(mx0, fmaxf(acc[nt][0], acc[nt][1]));
        mx1 = fmaxf(mx1, fmaxf(acc[nt][2], acc[nt][3]));
    }
    mx0 = fmaxf(mx0, __shfl_xor_sync(0xffffffffu, mx0, 1));
    mx0 = fmaxf(mx0, __shfl_xor_sync(0xffffffffu, mx0, 2));
    mx1 = fmaxf(mx1, __shfl_xor_sync(0xffffffffu, mx1, 1));
    mx1 = fmaxf(mx1, __shfl_xor_sync(0xffffffffu, mx1, 2));

    float sum0 = 0.f, sum1 = 0.f;
#pragma unroll
    for (int nt = 0; nt < 8; nt++) {
        acc[nt][0] = __expf(acc[nt][0] - mx0);
        acc[nt][1] = __expf(acc[nt][1] - mx0);
        acc[nt][2] = __expf(acc[nt][2] - mx1);
        acc[nt][3] = __expf(acc[nt][3] - mx1);
        sum0 += acc[nt][0] + acc[nt][1];
        sum1 += acc[nt][2] + acc[nt][3];
    }
    sum0 += __shfl_xor_sync(0xffffffffu, sum0, 1);
    sum0 += __shfl_xor_sync(0xffffffffu, sum0, 2);
    sum1 += __shfl_xor_sync(0xffffffffu, sum1, 1);
    sum1 += __shfl_xor_sync(0xffffffffu, sum1, 2);

    // ---- PV: O = P V, P single fp16, V hi+mid (2 MMAs per tile) ----
    float oacc[4][4];
#pragma unroll
    for (int dt = 0; dt < 4; dt++)
#pragma unroll
        for (int e = 0; e < 4; e++) oacc[dt][e] = 0.f;

#pragma unroll
    for (int kt = 0; kt < 4; kt++) {
        uint32_t phf[4];
        phf[0] = pack_h2(acc[2 * kt][0],     acc[2 * kt][1]);
        phf[1] = pack_h2(acc[2 * kt][2],     acc[2 * kt][3]);
        phf[2] = pack_h2(acc[2 * kt + 1][0], acc[2 * kt + 1][1]);
        phf[3] = pack_h2(acc[2 * kt + 1][2], acc[2 * kt + 1][3]);

        uint32_t vh[2][4], vm[2][4];
#pragma unroll
        for (int d2 = 0; d2 < 2; d2++) {
            uint32_t off = (uint32_t)((d2 * 16 + bnp) * VT_STRIDE + (kt * 16 + bc8) * 2);
            ldmatrix_x4(vh[d2], smem_u32(vthi)  + off);
            ldmatrix_x4(vm[d2], smem_u32(vtmid) + off);
        }
#pragma unroll
        for (int dt = 0; dt < 4; dt++) {
            mma_f32acc(oacc[dt], phf, &vh[dt >> 1][(dt & 1) * 2]);
            mma_f32acc(oacc[dt], phf, &vm[dt >> 1][(dt & 1) * 2]);
        }
    }

    // ---- epilogue: normalize, fp16 split store ----
    const float inv0 = 1.f / sum0;
    const float inv1 = 1.f / sum1;
#pragma unroll
    for (int dt = 0; dt < 4; dt++) {
        int col = dt * 8 + coff;
        size_t a0 = ((size_t)(b * SEQ + r0)) * CDIM + h * HDIM + col;
        size_t a1 = ((size_t)(b * SEQ + r1)) * CDIM + h * HDIM + col;
        uint32_t h0, m0w, h1, m1w;
        split2h(oacc[dt][0] * inv0, oacc[dt][1] * inv0, h0, m0w);
        split2h(oacc[dt][2] * inv1, oacc[dt][3] * inv1, h1, m1w);
        *(uint32_t*)&g_att_hi[a0]  = h0;
        *(uint32_t*)&g_att_mid[a0] = m0w;
        *(uint32_t*)&g_att_hi[a1]  = h1;
        *(uint32_t*)&g_att_mid[a1] = m1w;
    }
}

// ---------------------------------------------------------------------------
extern "C" void kernel_launch(void* const* d_in, const int* in_sizes, int n_in,
                              void* d_out, int out_size)
{
    const float* x           = (const float*)d_in[0];
    const float* mask        = (const float*)d_in[1];
    const float* qkv_w       = (const float*)d_in[2];
    const float* qkv_b       = (const float*)d_in[3];
    const float* proj_w      = (const float*)d_in[4];
    const float* proj_b      = (const float*)d_in[5];
    const float* logit_scale = (const float*)d_in[6];
    float* out = (float*)d_out;

    float* qkv_ptr = nullptr;
    __half *xh, *xm, *ah, *am, *wqh, *wqm, *wph, *wpm;
    cudaGetSymbolAddress((void**)&qkv_ptr, g_qkv);
    cudaGetSymbolAddress((void**)&xh,  g_x_hi);
    cudaGetSymbolAddress((void**)&xm,  g_x_mid);
    cudaGetSymbolAddress((void**)&ah,  g_att_hi);
    cudaGetSymbolAddress((void**)&am,  g_att_mid);
    cudaGetSymbolAddress((void**)&wqh, g_wq_hi);
    cudaGetSymbolAddress((void**)&wqm, g_wq_mid);
    cudaGetSymbolAddress((void**)&wph, g_wp_hi);
    cudaGetSymbolAddress((void**)&wpm, g_wp_mid);

    cudaFuncSetAttribute(gemm_f16_kernel,
                         cudaFuncAttributeMaxDynamicSharedMemorySize,
                         SMEM_GEMM_BYTES);

    rope_init_kernel<<<1, 1024>>>();
    split_kernel<<<(MROWS * CDIM / 4 + 255) / 256, 256>>>(x, xh, xm,
                                                          MROWS * CDIM / 4);
    split_kernel<<<(QKVDIM * GK / 4 + 255) / 256, 256>>>(qkv_w, wqh, wqm,
                                                         QKVDIM * GK / 4);
    split_kernel<<<(CDIM * GK / 4 + 255) / 256, 256>>>(proj_w, wph, wpm,
                                                       CDIM * GK / 4);

    // 1) QKV GEMM
    {
        dim3 grid(QKVDIM / 64, MROWS / 128);
        gemm_f16_kernel<<<grid, 256, SMEM_GEMM_BYTES>>>(xh, xm, wqh, wqm,
                                                        qkv_b, qkv_ptr, QKVDIM);
    }
    // 2) Attention
    {
        dim3 grid(BATCH, HEADS);
        attn_mma_kernel<<<grid, 128>>>(mask, logit_scale);
    }
    // 3) Proj GEMM
    {
        dim3 grid(CDIM / 64, MROWS / 128);
        gemm_f16_kernel<<<grid, 256, SMEM_GEMM_BYTES>>>(ah, am, wph, wpm,
                                                        proj_b, out, CDIM);
    }
}